// round 10
// baseline (speedup 1.0000x reference)
#include <cuda_runtime.h>
#include <cstdint>

#define TASKS    128
#define NSAMP    2048
#define INDIM    256
#define OUTDIM   256
#define GRP      8            // samples per work item
#define ILEN     128          // i-rows per CTA (K split in 2)
#define MAXITEMS 384          // sum ceil(cnt/8) <= 2048/8 + 128
#define K2_GRID  (4 * MAXITEMS)   // item x col-half x i-half

__device__ unsigned short g_slist[NSAMP];
__device__ int2 g_items[MAXITEMS];   // x = base | (scount<<16), y = task
__device__ int g_nitems;
__device__ float g_part[2][NSAMP][OUTDIM];   // i-half partials (4MB, L2-resident)

__device__ __forceinline__ unsigned smem_u32(const void* p) {
    unsigned r;
    asm("{ .reg .u64 t; cvta.to.shared.u64 t, %1; cvt.u32.u64 %0, t; }" : "=r"(r) : "l"(p));
    return r;
}
__device__ __forceinline__ unsigned long long dup2(float f) {
    unsigned long long d; unsigned u = __float_as_uint(f);
    asm("mov.b64 %0, {%1, %1};" : "=l"(d) : "r"(u));
    return d;
}

// ---------------- K1: 1024-thread histogram + warp-shfl scans + worklist ----------------
__global__ __launch_bounds__(1024) void k1_scan(const void* __restrict__ TIDS)
{
    __shared__ int cnts[TASKS], cursor[TASKS];
    __shared__ int soff[TASKS + 1], ioff[TASKS];
    __shared__ unsigned orv;

    const int tid = threadIdx.x;
    if (tid < TASKS) { cnts[tid] = 0; cursor[tid] = 0; }
    if (tid == 0) orv = 0;
    __syncthreads();

    const unsigned* w32 = (const unsigned*)TIDS;
    // dtype detect: int64 iff hi 32-bit words are all zero over first 256 samples.
    if (tid < 256) atomicOr(&orv, w32[2 * tid + 1]);
    __syncthreads();
    const int shift = (orv == 0) ? 1 : 0;

    int id0, id1;
    {
        id0 = (int)w32[(unsigned)tid << shift];
        id1 = (int)w32[(unsigned)(tid + 1024) << shift];
        atomicAdd(&cnts[id0], 1);
        atomicAdd(&cnts[id1], 1);
    }
    __syncthreads();

    if (tid < 32) {                       // warp 0: both prefix scans via shfl
        int c[4], pc[4], pi[4];
        int sc = 0, si = 0;
        #pragma unroll
        for (int j = 0; j < 4; ++j) {
            c[j] = cnts[tid * 4 + j];
            pc[j] = sc; sc += c[j];
            pi[j] = si; si += (c[j] + GRP - 1) >> 3;
        }
        int vc = sc, vi = si;
        #pragma unroll
        for (int d = 1; d < 32; d <<= 1) {
            int uc = __shfl_up_sync(0xffffffffu, vc, d);
            int ui = __shfl_up_sync(0xffffffffu, vi, d);
            if (tid >= d) { vc += uc; vi += ui; }
        }
        const int ec = vc - sc, ei = vi - si;
        #pragma unroll
        for (int j = 0; j < 4; ++j) {
            soff[tid * 4 + j] = ec + pc[j];
            ioff[tid * 4 + j] = ei + pi[j];
        }
        if (tid == 31) { soff[TASKS] = ec + sc; g_nitems = ei + si; }
    }
    __syncthreads();

    if (tid < TASKS) {
        const int b = soff[tid], cnt = soff[tid + 1] - b, io = ioff[tid];
        for (int g = 0; g * GRP < cnt; ++g) {
            int rem = cnt - g * GRP; if (rem > GRP) rem = GRP;
            g_items[io + g] = make_int2((b + GRP * g) | (rem << 16), tid);
        }
    }
    {
        int p0 = atomicAdd(&cursor[id0], 1);
        g_slist[soff[id0] + p0] = (unsigned short)tid;
        int p1 = atomicAdd(&cursor[id1], 1);
        g_slist[soff[id1] + p1] = (unsigned short)(tid + 1024);
    }   // in-task order irrelevant: per-sample i-order is fixed -> deterministic output
}

// ---- K2: CTA = (8 samples x 128 cols x 128 i); thread = 1 col x 8 samples ----
// x rows broadcast-LDS, 4 buffers / 2-stage lookahead; W scalar, 16-deep prefetch.
__device__ __forceinline__ void stage(float& w, const float* __restrict__ pf, bool pm,
                                      unsigned long long (&xu)[4], unsigned long long (&xl)[4],
                                      unsigned la, unsigned long long (&acc)[4])
{
    const unsigned long long wd = dup2(w);
    if (pm) w = __ldg(pf);                           // prefetch W for i+16
    asm("ld.shared.v2.b64 {%0,%1},[%2];" : "=l"(xl[0]), "=l"(xl[1]) : "r"(la));
    asm("ld.shared.v2.b64 {%0,%1},[%2];" : "=l"(xl[2]), "=l"(xl[3]) : "r"(la + 16));
    asm("fma.rn.f32x2 %0, %1, %2, %0;" : "+l"(acc[0]) : "l"(xu[0]), "l"(wd));
    asm("fma.rn.f32x2 %0, %1, %2, %0;" : "+l"(acc[1]) : "l"(xu[1]), "l"(wd));
    asm("fma.rn.f32x2 %0, %1, %2, %0;" : "+l"(acc[2]) : "l"(xu[2]), "l"(wd));
    asm("fma.rn.f32x2 %0, %1, %2, %0;" : "+l"(acc[3]) : "l"(xu[3]), "l"(wd));
}

__global__ __launch_bounds__(128) void k2_gemm(const float* __restrict__ X,
                                               const float* __restrict__ W)
{
    __shared__ __align__(16) float xt[ILEN * GRP + 2 * GRP];  // 4KB + 64B pad
    __shared__ unsigned short sl[GRP];

    const int tid   = threadIdx.x;
    const int idx   = blockIdx.x;
    const int item  = idx >> 2;
    const int half  = (idx >> 1) & 1;
    const int ihalf = idx & 1;
    if (item >= g_nitems) return;

    const int2 it = g_items[item];
    const int base = it.x & 0xffff, scount = it.x >> 16, task = it.y;

    if (tid < GRP) sl[tid] = (tid < scount) ? g_slist[base + tid] : (unsigned short)0;

    {   // transposed tile fill (this i-half): (s = tid&7, q = tid>>3), 2 LDG.128 each
        const int s = tid & 7, q = tid >> 3;
        const bool valid = (s < scount);
        const float4* row = (const float4*)(X +
            (valid ? (unsigned)g_slist[base + s] * INDIM : 0u) + ihalf * ILEN);
        #pragma unroll
        for (int k = 0; k < 2; ++k) {
            const int iv = q + 16 * k;              // 0..31 float4-rows
            float4 v;
            if (valid) v = __ldg(row + iv);
            else       v = make_float4(0.f, 0.f, 0.f, 0.f);
            const int i = iv * 4;
            xt[(i + 0) * GRP + s] = v.x;
            xt[(i + 1) * GRP + s] = v.y;
            xt[(i + 2) * GRP + s] = v.z;
            xt[(i + 3) * GRP + s] = v.w;
        }
    }
    __syncthreads();

    const int o = half * 128 + tid;
    const float* Wb = W + (size_t)task * INDIM * OUTDIM + (size_t)ihalf * ILEN * OUTDIM + o;
    const unsigned xb = smem_u32(xt);

    unsigned long long acc[4];
    acc[0] = acc[1] = acc[2] = acc[3] = 0ull;

    float wA[8], wB[8];
    #pragma unroll
    for (int j = 0; j < 8; ++j) {
        wA[j] = __ldg(Wb + (size_t)j * OUTDIM);
        wB[j] = __ldg(Wb + (size_t)(8 + j) * OUTDIM);
    }

    // x pipeline: 4 buffers, 2-stage lookahead.
    unsigned long long X0[4], X1[4], X2[4], X3[4];
    asm("ld.shared.v2.b64 {%0,%1},[%2];" : "=l"(X0[0]), "=l"(X0[1]) : "r"(xb));
    asm("ld.shared.v2.b64 {%0,%1},[%2];" : "=l"(X0[2]), "=l"(X0[3]) : "r"(xb + 16));
    asm("ld.shared.v2.b64 {%0,%1},[%2];" : "=l"(X1[0]), "=l"(X1[1]) : "r"(xb + 32));
    asm("ld.shared.v2.b64 {%0,%1},[%2];" : "=l"(X1[2]), "=l"(X1[3]) : "r"(xb + 48));

    #pragma unroll 1
    for (int m = 0; m < 8; ++m) {                  // 16 i-values per iteration
        const bool pm = (m < 7);
        const unsigned ib = xb + (unsigned)m * (16 * 32);        // row i = 16m, 32B/row
        const float* Wp = Wb + (size_t)(16 * m + 16) * OUTDIM;   // prefetch base (i+16)
        stage(wA[0], Wp + 0  * OUTDIM, pm, X0, X2, ib + 2  * 32, acc);
        stage(wA[1], Wp + 1  * OUTDIM, pm, X1, X3, ib + 3  * 32, acc);
        stage(wA[2], Wp + 2  * OUTDIM, pm, X2, X0, ib + 4  * 32, acc);
        stage(wA[3], Wp + 3  * OUTDIM, pm, X3, X1, ib + 5  * 32, acc);
        stage(wA[4], Wp + 4  * OUTDIM, pm, X0, X2, ib + 6  * 32, acc);
        stage(wA[5], Wp + 5  * OUTDIM, pm, X1, X3, ib + 7  * 32, acc);
        stage(wA[6], Wp + 6  * OUTDIM, pm, X2, X0, ib + 8  * 32, acc);
        stage(wA[7], Wp + 7  * OUTDIM, pm, X3, X1, ib + 9  * 32, acc);
        stage(wB[0], Wp + 8  * OUTDIM, pm, X0, X2, ib + 10 * 32, acc);
        stage(wB[1], Wp + 9  * OUTDIM, pm, X1, X3, ib + 11 * 32, acc);
        stage(wB[2], Wp + 10 * OUTDIM, pm, X2, X0, ib + 12 * 32, acc);
        stage(wB[3], Wp + 11 * OUTDIM, pm, X3, X1, ib + 13 * 32, acc);
        stage(wB[4], Wp + 12 * OUTDIM, pm, X0, X2, ib + 14 * 32, acc);
        stage(wB[5], Wp + 13 * OUTDIM, pm, X1, X3, ib + 15 * 32, acc);
        stage(wB[6], Wp + 14 * OUTDIM, pm, X2, X0, ib + 16 * 32, acc);
        stage(wB[7], Wp + 15 * OUTDIM, pm, X3, X1, ib + 17 * 32, acc); // m=7: pad rows
    }

    float* P = &g_part[ihalf][0][0];
    #pragma unroll
    for (int p = 0; p < 4; ++p) {
        unsigned lo, hi;
        asm("mov.b64 {%0,%1},%2;" : "=r"(lo), "=r"(hi) : "l"(acc[p]));
        const int s0 = 2 * p, s1 = 2 * p + 1;
        if (s0 < scount) P[(size_t)sl[s0] * OUTDIM + o] = __uint_as_float(lo);
        if (s1 < scount) P[(size_t)sl[s1] * OUTDIM + o] = __uint_as_float(hi);
    }
}

// ---------------- K3: OUT = part0 + part1 (deterministic order) ----------------
__global__ __launch_bounds__(256) void k3_reduce(float* __restrict__ OUT)
{
    const int idx = blockIdx.x * 256 + threadIdx.x;   // float4 index
    const float4 a = ((const float4*)&g_part[0][0][0])[idx];
    const float4 b = ((const float4*)&g_part[1][0][0])[idx];
    ((float4*)OUT)[idx] = make_float4(a.x + b.x, a.y + b.y, a.z + b.z, a.w + b.w);
}

extern "C" void kernel_launch(void* const* d_in, const int* in_sizes, int n_in,
                              void* d_out, int out_size)
{
    const float* X    = (const float*)d_in[0];
    const void*  TIDS = d_in[1];
    const float* W    = (const float*)d_in[2];
    float*       OUT  = (float*)d_out;

    k1_scan<<<1, 1024>>>(TIDS);
    k2_gemm<<<K2_GRID, 128>>>(X, W);
    k3_reduce<<<(NSAMP * OUTDIM / 4) / 256, 256>>>(OUT);
}

// round 12
// speedup vs baseline: 1.0495x; 1.0495x over previous
#include <cuda_runtime.h>
#include <cstdint>

#define TASKS   128
#define NSAMP   2048
#define INDIM   256
#define OUTDIM  256
#define APITCH  260                     // floats; 260%32=4 -> conflict-free A frags
#define BPITCH  264                     // floats; 264%32=8 -> conflict-free B frags
#define KCH     16                      // k-rows per B chunk
#define NBUF    4
#define AHI_OFF 0
#define ALO_OFF (32 * APITCH * 4)
#define B_OFF   (2 * 32 * APITCH * 4)
#define BBUF_B  (KCH * BPITCH * 4)
#define DYN_BYTES (B_OFF + NBUF * BBUF_B + 16)

__device__ __forceinline__ unsigned smem_u32(const void* p) {
    unsigned r;
    asm("{ .reg .u64 t; cvta.to.shared.u64 t, %1; cvt.u32.u64 %0, t; }" : "=r"(r) : "l"(p));
    return r;
}
__device__ __forceinline__ float tf32r(float x) {
    unsigned u;
    asm("cvt.rna.tf32.f32 %0, %1;" : "=r"(u) : "f"(x));
    return __uint_as_float(u);
}
__device__ __forceinline__ void mma8(float (&d)[4], const unsigned (&a)[4],
                                     unsigned b0, unsigned b1) {
    asm volatile(
        "mma.sync.aligned.m16n8k8.row.col.f32.tf32.tf32.f32 "
        "{%0,%1,%2,%3},{%4,%5,%6,%7},{%8,%9},{%0,%1,%2,%3};"
        : "+f"(d[0]), "+f"(d[1]), "+f"(d[2]), "+f"(d[3])
        : "r"(a[0]), "r"(a[1]), "r"(a[2]), "r"(a[3]), "r"(b0), "r"(b1));
}
#define CP16(dst, src) \
    asm volatile("cp.async.cg.shared.global [%0], [%1], 16;" :: "r"(dst), "l"(src) : "memory")
#define CP_COMMIT() asm volatile("cp.async.commit_group;" ::: "memory")
#define CP_WAIT3()  asm volatile("cp.async.wait_group 3;" ::: "memory")
#define CP_WAIT0()  asm volatile("cp.async.wait_group 0;" ::: "memory")

__device__ __forceinline__ void issueB(const float* __restrict__ Wt, unsigned bbase,
                                       int kc, int tid) {
    const int row = tid >> 3, cg = tid & 7;             // 16 rows x 8 col-groups
    const float* src = Wt + (size_t)(kc * KCH + row) * OUTDIM + cg * 32;
    const unsigned dst = bbase + (unsigned)(row * BPITCH + cg * 32) * 4u;
    #pragma unroll
    for (int u = 0; u < 8; ++u)
        CP16(dst + 16u * (unsigned)u, src + 4 * u);
}

__global__ __launch_bounds__(128, 1)
void tsl_mma(const float* __restrict__ X, const void* __restrict__ TIDS,
             const float* __restrict__ W, float* __restrict__ OUT)
{
    extern __shared__ __align__(16) char dyn[];
    __shared__ unsigned short sl[NSAMP];
    __shared__ int s_cnt;
    __shared__ unsigned orv;

    const int tid = threadIdx.x, wid = tid >> 5, lane = tid & 31;
    const int l4 = lane >> 2, lm = lane & 3;
    const int task = blockIdx.x;
    const int nb = wid * 64;                            // warp's n-base

    const float* Wt = W + (size_t)task * INDIM * OUTDIM;
    const unsigned bbase0 = smem_u32(dyn + B_OFF);

    if (tid == 0) { s_cnt = 0; orv = 0; }

    // ---- prefetch first 4 B chunks BEFORE the id scan (hide DRAM behind scan) ----
    #pragma unroll
    for (int c = 0; c < NBUF; ++c) {
        issueB(Wt, bbase0 + (unsigned)c * BBUF_B, c, tid);
        CP_COMMIT();
    }
    __syncthreads();

    // ---- id scan: dtype-detect + ballot-compress this task's sample list ----
    const unsigned* w32 = (const unsigned*)TIDS;
    atomicOr(&orv, w32[2 * tid + 1] | w32[2 * (tid + 128) + 1]);  // int64 iff hi words 0
    __syncthreads();
    const bool is64 = (orv == 0);

    #pragma unroll 1
    for (int j = 0; j < 16; ++j) {
        const int n = j * 128 + tid;
        const int id = is64 ? (int)w32[2 * n] : (int)w32[n];
        const bool m = (id == task);
        const unsigned bal = __ballot_sync(0xffffffffu, m);
        if (bal) {
            int b = 0;
            if (lane == 0) b = atomicAdd(&s_cnt, __popc(bal));
            b = __shfl_sync(0xffffffffu, b, 0);
            if (m) sl[b + __popc(bal & ((1u << lane) - 1u))] = (unsigned short)n;
        }
    }
    __syncthreads();
    const int cnt = s_cnt;
    if (cnt == 0) { CP_WAIT0(); return; }

    float* Ah = (float*)(dyn + AHI_OFF);
    float* Al = (float*)(dyn + ALO_OFF);

    #pragma unroll 1
    for (int mc = 0; mc * 32 < cnt; ++mc) {
        if (mc > 0) {                                   // rare: re-stream W (L2-hot)
            #pragma unroll
            for (int c = 0; c < NBUF; ++c) {
                issueB(Wt, bbase0 + (unsigned)c * BBUF_B, c, tid);
                CP_COMMIT();
            }
        }

        // ---- fill A (32 rows x 256 k) as tf32 hi/lo; invalid rows -> zeros ----
        {
            const int s = tid >> 2, q = tid & 3;        // row, quarter
            const int g = mc * 32 + s;
            const bool valid = (g < cnt);
            const float4* xr = (const float4*)(X + (valid ? (unsigned)sl[g] * INDIM : 0u))
                               + q * 16;
            #pragma unroll
            for (int j = 0; j < 16; ++j) {
                float4 v = valid ? __ldg(xr + j) : make_float4(0.f, 0.f, 0.f, 0.f);
                float4 h = make_float4(tf32r(v.x), tf32r(v.y), tf32r(v.z), tf32r(v.w));
                float4 l = make_float4(tf32r(v.x - h.x), tf32r(v.y - h.y),
                                       tf32r(v.z - h.z), tf32r(v.w - h.w));
                const int o = s * APITCH + q * 64 + 4 * j;
                *(float4*)(Ah + o) = h;
                *(float4*)(Al + o) = l;
            }
        }
        __syncthreads();

        float cacc[2][8][4];
        #pragma unroll
        for (int mt = 0; mt < 2; ++mt)
            #pragma unroll
            for (int nt = 0; nt < 8; ++nt)
                #pragma unroll
                for (int p = 0; p < 4; ++p) cacc[mt][nt][p] = 0.f;

        #pragma unroll 1
        for (int kc = 0; kc < INDIM / KCH; ++kc) {
            CP_WAIT3();
            __syncthreads();
            const float* Bb = (const float*)(dyn + B_OFF + (kc & 3) * BBUF_B);

            #pragma unroll
            for (int h = 0; h < 2; ++h) {               // two k8 halves
                const int cb = kc * KCH + h * 8 + lm;
                unsigned a0h[4], a0l[4], a1h[4], a1l[4];
                a0h[0] = __float_as_uint(Ah[(l4)      * APITCH + cb]);
                a0h[1] = __float_as_uint(Ah[(l4 + 8)  * APITCH + cb]);
                a0h[2] = __float_as_uint(Ah[(l4)      * APITCH + cb + 4]);
                a0h[3] = __float_as_uint(Ah[(l4 + 8)  * APITCH + cb + 4]);
                a1h[0] = __float_as_uint(Ah[(l4 + 16) * APITCH + cb]);
                a1h[1] = __float_as_uint(Ah[(l4 + 24) * APITCH + cb]);
                a1h[2] = __float_as_uint(Ah[(l4 + 16) * APITCH + cb + 4]);
                a1h[3] = __float_as_uint(Ah[(l4 + 24) * APITCH + cb + 4]);
                a0l[0] = __float_as_uint(Al[(l4)      * APITCH + cb]);
                a0l[1] = __float_as_uint(Al[(l4 + 8)  * APITCH + cb]);
                a0l[2] = __float_as_uint(Al[(l4)      * APITCH + cb + 4]);
                a0l[3] = __float_as_uint(Al[(l4 + 8)  * APITCH + cb + 4]);
                a1l[0] = __float_as_uint(Al[(l4 + 16) * APITCH + cb]);
                a1l[1] = __float_as_uint(Al[(l4 + 24) * APITCH + cb]);
                a1l[2] = __float_as_uint(Al[(l4 + 16) * APITCH + cb + 4]);
                a1l[3] = __float_as_uint(Al[(l4 + 24) * APITCH + cb + 4]);

                const int kl = h * 8 + lm;
                #pragma unroll
                for (int nt = 0; nt < 8; ++nt) {
                    const int n = nb + nt * 8 + l4;
                    const float w0 = Bb[(kl)     * BPITCH + n];
                    const float w1 = Bb[(kl + 4) * BPITCH + n];
                    const float bh0 = tf32r(w0), bh1 = tf32r(w1);
                    const float bl0 = tf32r(w0 - bh0), bl1 = tf32r(w1 - bh1);
                    const unsigned ubh0 = __float_as_uint(bh0), ubh1 = __float_as_uint(bh1);
                    const unsigned ubl0 = __float_as_uint(bl0), ubl1 = __float_as_uint(bl1);
                    mma8(cacc[0][nt], a0h, ubh0, ubh1);   // hi*hi
                    mma8(cacc[0][nt], a0l, ubh0, ubh1);   // lo*hi
                    mma8(cacc[0][nt], a0h, ubl0, ubl1);   // hi*lo
                    mma8(cacc[1][nt], a1h, ubh0, ubh1);
                    mma8(cacc[1][nt], a1l, ubh0, ubh1);
                    mma8(cacc[1][nt], a1h, ubl0, ubl1);
                }
            }
            __syncthreads();
            if (kc + NBUF < INDIM / KCH)
                issueB(Wt, bbase0 + (unsigned)(kc & 3) * BBUF_B, kc + NBUF, tid);
            CP_COMMIT();                                // empty groups keep accounting uniform
        }

        // ---- store C fragments ----
        #pragma unroll
        for (int mt = 0; mt < 2; ++mt) {
            #pragma unroll
            for (int nt = 0; nt < 8; ++nt) {
                const int col = nb + nt * 8 + 2 * lm;
                const int r0 = mc * 32 + mt * 16 + l4;
                if (r0 < cnt)
                    *(float2*)(OUT + (size_t)sl[r0] * OUTDIM + col)
                        = make_float2(cacc[mt][nt][0], cacc[mt][nt][1]);
                const int r1 = r0 + 8;
                if (r1 < cnt)
                    *(float2*)(OUT + (size_t)sl[r1] * OUTDIM + col)
                        = make_float2(cacc[mt][nt][2], cacc[mt][nt][3]);
            }
        }
    }
    CP_WAIT0();
}

extern "C" void kernel_launch(void* const* d_in, const int* in_sizes, int n_in,
                              void* d_out, int out_size)
{
    const float* X    = (const float*)d_in[0];
    const void*  TIDS = d_in[1];
    const float* W    = (const float*)d_in[2];
    float*       OUT  = (float*)d_out;

    cudaFuncSetAttribute(tsl_mma, cudaFuncAttributeMaxDynamicSharedMemorySize, DYN_BYTES);
    tsl_mma<<<TASKS, 128, DYN_BYTES>>>(X, TIDS, W, OUT);
}

// round 13
// speedup vs baseline: 1.0705x; 1.0200x over previous
#include <cuda_runtime.h>
#include <cstdint>

#define TASKS   128
#define NSAMP   2048
#define INDIM   256
#define OUTDIM  256
#define APITCH  260                     // floats; %32=4 -> conflict-free A frags
#define BPITCH  264                     // floats; %32=8 -> conflict-free B frags
#define KCH     16                      // k-rows per B chunk
#define NBUF    4
#define AHI_OFF 0
#define ALO_OFF (32 * APITCH * 4)
#define B_OFF   (2 * 32 * APITCH * 4)
#define BBUF_B  (KCH * BPITCH * 4)
#define DYN_BYTES (B_OFF + NBUF * BBUF_B + 16)

__device__ __forceinline__ unsigned smem_u32(const void* p) {
    unsigned r;
    asm("{ .reg .u64 t; cvta.to.shared.u64 t, %1; cvt.u32.u64 %0, t; }" : "=r"(r) : "l"(p));
    return r;
}
__device__ __forceinline__ float tf32r(float x) {
    unsigned u;
    asm("cvt.rna.tf32.f32 %0, %1;" : "=r"(u) : "f"(x));
    return __uint_as_float(u);
}
__device__ __forceinline__ void mma8(float (&d)[4], const unsigned (&a)[4],
                                     unsigned b0, unsigned b1) {
    asm volatile(
        "mma.sync.aligned.m16n8k8.row.col.f32.tf32.tf32.f32 "
        "{%0,%1,%2,%3},{%4,%5,%6,%7},{%8,%9},{%0,%1,%2,%3};"
        : "+f"(d[0]), "+f"(d[1]), "+f"(d[2]), "+f"(d[3])
        : "r"(a[0]), "r"(a[1]), "r"(a[2]), "r"(a[3]), "r"(b0), "r"(b1));
}
#define CP16(dst, src) \
    asm volatile("cp.async.cg.shared.global [%0], [%1], 16;" :: "r"(dst), "l"(src) : "memory")
#define CP_COMMIT() asm volatile("cp.async.commit_group;" ::: "memory")
#define CP_WAIT3()  asm volatile("cp.async.wait_group 3;" ::: "memory")
#define CP_WAIT0()  asm volatile("cp.async.wait_group 0;" ::: "memory")

// 256 threads: row = tid>>4 (16 rows), cg = tid&15 (16 col-groups of 16 floats)
__device__ __forceinline__ void issueB(const float* __restrict__ Wt, unsigned bbase,
                                       int kc, int tid) {
    const int row = tid >> 4, cg = tid & 15;
    const float* src = Wt + (size_t)(kc * KCH + row) * OUTDIM + cg * 16;
    const unsigned dst = bbase + (unsigned)(row * BPITCH + cg * 16) * 4u;
    #pragma unroll
    for (int u = 0; u < 4; ++u)
        CP16(dst + 16u * (unsigned)u, src + 4 * u);
}

__global__ __launch_bounds__(256, 1)
void tsl_mma(const float* __restrict__ X, const void* __restrict__ TIDS,
             const float* __restrict__ W, float* __restrict__ OUT)
{
    extern __shared__ __align__(16) char dyn[];
    __shared__ unsigned short sl[NSAMP];
    __shared__ int s_cnt;
    __shared__ unsigned orv;

    const int tid = threadIdx.x, wid = tid >> 5, lane = tid & 31;
    const int l4 = lane >> 2, lm = lane & 3;
    const int task = blockIdx.x;
    const int nb = wid * 32;                            // warp's n-base (4 N-tiles)

    const float* Wt = W + (size_t)task * INDIM * OUTDIM;
    const unsigned bbase0 = smem_u32(dyn + B_OFF);

    if (tid == 0) { s_cnt = 0; orv = 0; }

    // ---- prefetch first 4 B chunks BEFORE the id scan (hide DRAM behind scan) ----
    #pragma unroll
    for (int c = 0; c < NBUF; ++c) {
        issueB(Wt, bbase0 + (unsigned)c * BBUF_B, c, tid);
        CP_COMMIT();
    }
    __syncthreads();

    // ---- id scan: dtype-detect + ballot-compress this task's sample list ----
    const unsigned* w32 = (const unsigned*)TIDS;
    atomicOr(&orv, w32[2 * tid + 1]);                   // int64 iff hi words (0..255) all 0
    __syncthreads();
    const bool is64 = (orv == 0);

    #pragma unroll 1
    for (int j = 0; j < 8; ++j) {
        const int n = j * 256 + tid;
        const int id = is64 ? (int)w32[2 * n] : (int)w32[n];
        const bool m = (id == task);
        const unsigned bal = __ballot_sync(0xffffffffu, m);
        if (bal) {
            int b = 0;
            if (lane == 0) b = atomicAdd(&s_cnt, __popc(bal));
            b = __shfl_sync(0xffffffffu, b, 0);
            if (m) sl[b + __popc(bal & ((1u << lane) - 1u))] = (unsigned short)n;
        }
    }
    __syncthreads();
    const int cnt = s_cnt;
    if (cnt == 0) { CP_WAIT0(); return; }

    float* Ah = (float*)(dyn + AHI_OFF);
    float* Al = (float*)(dyn + ALO_OFF);

    #pragma unroll 1
    for (int mc = 0; mc * 32 < cnt; ++mc) {
        if (mc > 0) {                                   // rare: re-stream W (L2-hot)
            #pragma unroll
            for (int c = 0; c < NBUF; ++c) {
                issueB(Wt, bbase0 + (unsigned)c * BBUF_B, c, tid);
                CP_COMMIT();
            }
        }
        const bool two = (cnt - mc * 32) > 16;          // is the upper m16 tile non-empty?

        // ---- fill A (32 rows x 256 k) as tf32 hi/lo; invalid rows -> zeros ----
        {
            const int s = tid >> 3, q = tid & 7;        // row, eighth
            const int g = mc * 32 + s;
            const bool valid = (g < cnt);
            const float4* xr = (const float4*)(X + (valid ? (unsigned)sl[g] * INDIM : 0u))
                               + q * 8;
            #pragma unroll
            for (int j = 0; j < 8; ++j) {
                float4 v = valid ? __ldg(xr + j) : make_float4(0.f, 0.f, 0.f, 0.f);
                float4 h = make_float4(tf32r(v.x), tf32r(v.y), tf32r(v.z), tf32r(v.w));
                float4 l = make_float4(tf32r(v.x - h.x), tf32r(v.y - h.y),
                                       tf32r(v.z - h.z), tf32r(v.w - h.w));
                const int o = s * APITCH + q * 32 + 4 * j;
                *(float4*)(Ah + o) = h;
                *(float4*)(Al + o) = l;
            }
        }
        __syncthreads();

        float cacc[2][4][4];
        #pragma unroll
        for (int mt = 0; mt < 2; ++mt)
            #pragma unroll
            for (int nt = 0; nt < 4; ++nt)
                #pragma unroll
                for (int p = 0; p < 4; ++p) cacc[mt][nt][p] = 0.f;

        #pragma unroll 1
        for (int kc = 0; kc < INDIM / KCH; ++kc) {
            CP_WAIT3();
            __syncthreads();
            const float* Bb = (const float*)(dyn + B_OFF + (kc & 3) * BBUF_B);

            #pragma unroll
            for (int h = 0; h < 2; ++h) {               // two k8 halves
                const int cb = kc * KCH + h * 8 + lm;
                const int kl = h * 8 + lm;

                // B fragments for this half: 4 N-tiles, hi/lo
                unsigned ubh0[4], ubh1[4], ubl0[4], ubl1[4];
                #pragma unroll
                for (int nt = 0; nt < 4; ++nt) {
                    const int n = nb + nt * 8 + l4;
                    const float w0 = Bb[(kl)     * BPITCH + n];
                    const float w1 = Bb[(kl + 4) * BPITCH + n];
                    const float bh0 = tf32r(w0), bh1 = tf32r(w1);
                    ubh0[nt] = __float_as_uint(bh0);
                    ubh1[nt] = __float_as_uint(bh1);
                    ubl0[nt] = __float_as_uint(tf32r(w0 - bh0));
                    ubl1[nt] = __float_as_uint(tf32r(w1 - bh1));
                }

                {   // lower m16 tile (rows 0..15)
                    unsigned ah[4], al[4];
                    ah[0] = __float_as_uint(Ah[(l4)     * APITCH + cb]);
                    ah[1] = __float_as_uint(Ah[(l4 + 8) * APITCH + cb]);
                    ah[2] = __float_as_uint(Ah[(l4)     * APITCH + cb + 4]);
                    ah[3] = __float_as_uint(Ah[(l4 + 8) * APITCH + cb + 4]);
                    al[0] = __float_as_uint(Al[(l4)     * APITCH + cb]);
                    al[1] = __float_as_uint(Al[(l4 + 8) * APITCH + cb]);
                    al[2] = __float_as_uint(Al[(l4)     * APITCH + cb + 4]);
                    al[3] = __float_as_uint(Al[(l4 + 8) * APITCH + cb + 4]);
                    #pragma unroll
                    for (int nt = 0; nt < 4; ++nt) {
                        mma8(cacc[0][nt], ah, ubh0[nt], ubh1[nt]);   // hi*hi
                        mma8(cacc[0][nt], al, ubh0[nt], ubh1[nt]);   // lo*hi
                        mma8(cacc[0][nt], ah, ubl0[nt], ubl1[nt]);   // hi*lo
                    }
                }
                if (two) {   // upper m16 tile (rows 16..31), skipped when all-pad
                    unsigned ah[4], al[4];
                    ah[0] = __float_as_uint(Ah[(l4 + 16) * APITCH + cb]);
                    ah[1] = __float_as_uint(Ah[(l4 + 24) * APITCH + cb]);
                    ah[2] = __float_as_uint(Ah[(l4 + 16) * APITCH + cb + 4]);
                    ah[3] = __float_as_uint(Ah[(l4 + 24) * APITCH + cb + 4]);
                    al[0] = __float_as_uint(Al[(l4 + 16) * APITCH + cb]);
                    al[1] = __float_as_uint(Al[(l4 + 24) * APITCH + cb]);
                    al[2] = __float_as_uint(Al[(l4 + 16) * APITCH + cb + 4]);
                    al[3] = __float_as_uint(Al[(l4 + 24) * APITCH + cb + 4]);
                    #pragma unroll
                    for (int nt = 0; nt < 4; ++nt) {
                        mma8(cacc[1][nt], ah, ubh0[nt], ubh1[nt]);
                        mma8(cacc[1][nt], al, ubh0[nt], ubh1[nt]);
                        mma8(cacc[1][nt], ah, ubl0[nt], ubl1[nt]);
                    }
                }
            }
            __syncthreads();
            if (kc + NBUF < INDIM / KCH)
                issueB(Wt, bbase0 + (unsigned)(kc & 3) * BBUF_B, kc + NBUF, tid);
            CP_COMMIT();                                // empty groups keep accounting uniform
        }

        // ---- store C fragments ----
        #pragma unroll
        for (int mt = 0; mt < 2; ++mt) {
            #pragma unroll
            for (int nt = 0; nt < 4; ++nt) {
                const int col = nb + nt * 8 + 2 * lm;
                const int r0 = mc * 32 + mt * 16 + l4;
                if (r0 < cnt)
                    *(float2*)(OUT + (size_t)sl[r0] * OUTDIM + col)
                        = make_float2(cacc[mt][nt][0], cacc[mt][nt][1]);
                const int r1 = r0 + 8;
                if (r1 < cnt)
                    *(float2*)(OUT + (size_t)sl[r1] * OUTDIM + col)
                        = make_float2(cacc[mt][nt][2], cacc[mt][nt][3]);
            }
        }
    }
    CP_WAIT0();
}

extern "C" void kernel_launch(void* const* d_in, const int* in_sizes, int n_in,
                              void* d_out, int out_size)
{
    const float* X    = (const float*)d_in[0];
    const void*  TIDS = d_in[1];
    const float* W    = (const float*)d_in[2];
    float*       OUT  = (float*)d_out;

    cudaFuncSetAttribute(tsl_mma, cudaFuncAttributeMaxDynamicSharedMemorySize, DYN_BYTES);
    tsl_mma<<<TASKS, 256, DYN_BYTES>>>(X, TIDS, W, OUT);
}